// round 1
// baseline (speedup 1.0000x reference)
#include <cuda_runtime.h>
#include <math.h>

#define BB 32
#define NN 2048
#define VD 256
#define LR 64
#define EMB 256

typedef unsigned long long ull;

// ---------------- device scratch (no allocations allowed) ----------------
__device__ __align__(16) float g_Wt[VD * 128];     // W concat, TRANSPOSED: [k][128]; cols 0..63 = W1(right), 64..127 = W2(left)
__device__ __align__(16) float g_bias[128];        // b1 | b2
__device__ __align__(16) float g_rd[BB * NN * LR]; // dr[b,m] * right[b,m,l]   (16 MB)
__device__ float g_s[BB * LR];                     // sum_n dr*left
__device__ float g_sumV[BB * VD];                  // sum_m V
__device__ float g_w[BB * VD];                     // sum_m dr*t*V

// ---------------- packed f32x2 helpers ----------------
__device__ __forceinline__ void ffma2(ull &acc, ull a, ull b) {
    asm volatile("fma.rn.f32x2 %0, %1, %2, %0;" : "+l"(acc) : "l"(a), "l"(b));
}
__device__ __forceinline__ ull pack2(float lo, float hi) {
    ull r; asm("mov.b64 %0, {%1, %2};" : "=l"(r) : "f"(lo), "f"(hi)); return r;
}
__device__ __forceinline__ float2 unpack2(ull v) {
    float2 r; asm("mov.b64 {%0, %1}, %2;" : "=f"(r.x), "=f"(r.y) : "l"(v)); return r;
}

// ---------------- K0: weight-norm prep + zero accumulators ----------------
__global__ void k_prep(const float* __restrict__ U1v, const float* __restrict__ U1g,
                       const float* __restrict__ U1b, const float* __restrict__ U2v,
                       const float* __restrict__ U2g, const float* __restrict__ U2b) {
    int tid = threadIdx.x;
    if (blockIdx.x == 0) {
        if (tid < 128) {
            int i = tid;
            const float* v; float g, bv;
            if (i < LR) { v = U1v + i * VD; g = U1g[i]; bv = U1b[i]; }
            else        { v = U2v + (i - LR) * VD; g = U2g[i - LR]; bv = U2b[i - LR]; }
            float ss = 0.f;
            for (int k = 0; k < VD; k++) { float x = v[k]; ss += x * x; }
            float sc = g / sqrtf(ss);
            for (int k = 0; k < VD; k++) g_Wt[k * 128 + i] = v[k] * sc;
            g_bias[i] = bv;
        }
    } else {
        const int total = BB * LR + BB * VD + BB * VD;
        int stride = (gridDim.x - 1) * blockDim.x;
        for (int idx = (blockIdx.x - 1) * blockDim.x + tid; idx < total; idx += stride) {
            if (idx < BB * LR) g_s[idx] = 0.f;
            else if (idx < BB * LR + BB * VD) g_sumV[idx - BB * LR] = 0.f;
            else g_w[idx - BB * LR - BB * VD] = 0.f;
        }
    }
}

// ---------------- K1: projections + dr + rd + s-partials ----------------
#define AS_STRIDE 72
#define BS_STRIDE 136
#define OUT_STRIDE 130
#define AS_FLOATS (VD * AS_STRIDE)   // 18432
#define BS_FLOATS (VD * BS_STRIDE)   // 34816
#define SM1_FLOATS (AS_FLOATS + BS_FLOATS + 128 + 192)

__global__ __launch_bounds__(256, 1) void k_proj(const float* __restrict__ V) {
    extern __shared__ float sm[];
    float* As    = sm;                 // V tile transposed: [k=256][row=64 (+pad)]
    float* Bs    = sm + AS_FLOATS;     // W: [k=256][col=128 (+pad)]
    float* biass = Bs + BS_FLOATS;     // [128]
    float* dpart = biass + 128;        // [128]
    float* drb   = dpart + 128;        // [64]

    int tid = threadIdx.x;
    int b   = blockIdx.y;
    int m0  = blockIdx.x * 64;

    if (tid < 128) biass[tid] = g_bias[tid];

    // load W (coalesced, already transposed in global)
    {
        const float4* wsrc = (const float4*)g_Wt;
        for (int i = tid; i < VD * 32; i += 256) {
            int k = i >> 5, c = (i & 31) << 2;
            *(float4*)(Bs + k * BS_STRIDE + c) = wsrc[i];
        }
    }
    // load V tile, transpose into As
    {
        const float4* vsrc = (const float4*)(V + ((size_t)b * NN + m0) * VD);
        for (int i = tid; i < 64 * 64; i += 256) {
            int r = i >> 6, d4 = i & 63;
            float4 v = vsrc[r * 64 + d4];
            int dd = d4 << 2;
            As[(dd + 0) * AS_STRIDE + r] = v.x;
            As[(dd + 1) * AS_STRIDE + r] = v.y;
            As[(dd + 2) * AS_STRIDE + r] = v.z;
            As[(dd + 3) * AS_STRIDE + r] = v.w;
        }
    }
    __syncthreads();

    int tcol4 = (tid & 31) << 2;  // col base: 0..124
    int trow  = (tid >> 5) << 3;  // row base: 0..56

    ull acc[4][4];
#pragma unroll
    for (int i = 0; i < 4; i++)
#pragma unroll
        for (int j = 0; j < 4; j++) acc[i][j] = 0ull;

    const float* ap = As + trow;
    const float* bp = Bs + tcol4;

#pragma unroll 4
    for (int k = 0; k < VD; k++) {
        ulonglong2 aL = *(const ulonglong2*)(ap + k * AS_STRIDE);      // rows trow..trow+3 (as 2 f32 pairs)
        ulonglong2 aH = *(const ulonglong2*)(ap + k * AS_STRIDE + 4);  // rows trow+4..trow+7
        float4 bq = *(const float4*)(bp + k * BS_STRIDE);
        ull b0 = pack2(bq.x, bq.x), b1 = pack2(bq.y, bq.y);
        ull b2 = pack2(bq.z, bq.z), b3 = pack2(bq.w, bq.w);
        ull ar0 = aL.x, ar1 = aL.y, ar2 = aH.x, ar3 = aH.y;
        ffma2(acc[0][0], ar0, b0); ffma2(acc[0][1], ar0, b1); ffma2(acc[0][2], ar0, b2); ffma2(acc[0][3], ar0, b3);
        ffma2(acc[1][0], ar1, b0); ffma2(acc[1][1], ar1, b1); ffma2(acc[1][2], ar1, b2); ffma2(acc[1][3], ar1, b3);
        ffma2(acc[2][0], ar2, b0); ffma2(acc[2][1], ar2, b1); ffma2(acc[2][2], ar2, b2); ffma2(acc[2][3], ar2, b3);
        ffma2(acc[3][0], ar3, b0); ffma2(acc[3][1], ar3, b1); ffma2(acc[3][2], ar3, b2); ffma2(acc[3][3], ar3, b3);
    }
    __syncthreads();

    // bias + relu, into out buffer (reuse Bs region): [64][130]
    float* outb = Bs;
#pragma unroll
    for (int rp = 0; rp < 4; rp++) {
        int row = trow + 2 * rp;
#pragma unroll
        for (int c = 0; c < 4; c++) {
            int col = tcol4 + c;
            float2 v = unpack2(acc[rp][c]);
            float bia = biass[col];
            outb[row * OUT_STRIDE + col]       = fmaxf(v.x + bia, 0.f);
            outb[(row + 1) * OUT_STRIDE + col] = fmaxf(v.y + bia, 0.f);
        }
    }
    __syncthreads();

    // per-row diagonal d = sum_l right*left, dr = rsqrt(d + eps)
    if (tid < 128) {
        int r = tid >> 1, h = tid & 1;
        const float* orow = outb + r * OUT_STRIDE;
        float s = 0.f;
        int l0 = h * 32;
#pragma unroll 8
        for (int l = l0; l < l0 + 32; l++) s += orow[l] * orow[64 + l];
        dpart[tid] = s;
    }
    __syncthreads();
    if (tid < 64) drb[tid] = rsqrtf(dpart[2 * tid] + dpart[2 * tid + 1] + 1e-6f);
    __syncthreads();

    // write rd = dr * right  (coalesced float4)
    {
        float* rdst = g_rd + ((size_t)b * NN + m0) * LR;
        for (int i = tid; i < 64 * 16; i += 256) {
            int r = i >> 4, l = (i & 15) << 2;
            float dr = drb[r];
            const float* orow = outb + r * OUT_STRIDE + l;
            float4 o = make_float4(orow[0] * dr, orow[1] * dr, orow[2] * dr, orow[3] * dr);
            *(float4*)(rdst + r * LR + l) = o;
        }
    }
    // s partials: s[l] += sum_rows dr * left
    if (tid < 128) {
        int l = tid & 63, h = tid >> 6;
        float s = 0.f;
        int r0 = h * 32;
        for (int r = r0; r < r0 + 32; r++) s += drb[r] * outb[r * OUT_STRIDE + 64 + l];
        dpart[tid] = s;
    }
    __syncthreads();
    if (tid < 64) atomicAdd(&g_s[b * LR + tid], dpart[tid] + dpart[tid + 64]);
}

// ---------------- K3: t' = rd·s ; w = sum_m t'·V ; sumV ----------------
__global__ __launch_bounds__(256) void k_corrsum(const float* __restrict__ V) {
    __shared__ float ssm[LR];
    __shared__ float tsm[128];
    int tid = threadIdx.x;
    int b  = blockIdx.y;
    int m0 = blockIdx.x * 128;

    if (tid < LR) ssm[tid] = g_s[b * LR + tid];
    __syncthreads();

    if (tid < 128) {
        const float4* rdp = (const float4*)(g_rd + ((size_t)b * NN + m0 + tid) * LR);
        float tp = 0.f;
#pragma unroll
        for (int j = 0; j < 16; j++) {
            float4 r4 = rdp[j];
            const float* sl = ssm + j * 4;
            tp += r4.x * sl[0] + r4.y * sl[1] + r4.z * sl[2] + r4.w * sl[3];
        }
        tsm[tid] = tp;
    }
    __syncthreads();

    int d = tid;
    const float* vp = V + ((size_t)b * NN + m0) * VD + d;
    float w = 0.f, sv = 0.f;
#pragma unroll 8
    for (int m = 0; m < 128; m++) {
        float v = vp[m * VD];
        w += tsm[m] * v;
        sv += v;
    }
    atomicAdd(&g_w[b * VD + d], w);
    atomicAdd(&g_sumV[b * VD + d], sv);
}

// ---------------- K4: v_final -> linear -> batchnorm -> out ----------------
__global__ __launch_bounds__(256) void k_final(const float* __restrict__ Wlin,
                                               const float* __restrict__ blin,
                                               const float* __restrict__ gamma,
                                               const float* __restrict__ beta,
                                               float* __restrict__ out) {
    __shared__ float vf[BB * VD];     // 32 KB
    __shared__ float fe[16][33];
    __shared__ float sca[16], shf[16];
    int tid = threadIdx.x;
    int e0 = blockIdx.x * 16;
    const float invN = 1.0f / (float)NN;

    for (int i = tid; i < BB * VD; i += 256)
        vf[i] = ((float)(NN + 1) * g_sumV[i] - g_w[i]) * invN;
    __syncthreads();

    int el = tid >> 4;   // 0..15 (e within block)
    int bl = tid & 15;   // 0..15 (handles batches bl and bl+16)
    int e = e0 + el;
    const float4* wrow = (const float4*)(Wlin + (size_t)e * VD);
    const float* v0 = vf + bl * VD;
    const float* v1 = vf + (bl + 16) * VD;
    float a0 = 0.f, a1 = 0.f;
#pragma unroll 8
    for (int j = 0; j < 64; j++) {
        float4 w4 = __ldg(wrow + j);
        int dd = j * 4;
        a0 += w4.x * v0[dd] + w4.y * v0[dd + 1] + w4.z * v0[dd + 2] + w4.w * v0[dd + 3];
        a1 += w4.x * v1[dd] + w4.y * v1[dd + 1] + w4.z * v1[dd + 2] + w4.w * v1[dd + 3];
    }
    float bia = blin[e];
    fe[el][bl]      = a0 + bia;
    fe[el][bl + 16] = a1 + bia;
    __syncthreads();

    if (tid < 16) {
        int ee = e0 + tid;
        float mu = 0.f;
        for (int i = 0; i < BB; i++) mu += fe[tid][i];
        mu *= (1.0f / BB);
        float var = 0.f;
        for (int i = 0; i < BB; i++) { float dlt = fe[tid][i] - mu; var += dlt * dlt; }
        var *= (1.0f / BB);
        float s = rsqrtf(var + 1e-5f) * gamma[ee];
        sca[tid] = s;
        shf[tid] = beta[ee] - mu * s;
    }
    __syncthreads();

    out[bl * EMB + e]        = fe[el][bl] * sca[el] + shf[el];
    out[(bl + 16) * EMB + e] = fe[el][bl + 16] * sca[el] + shf[el];
}

// ---------------- launch ----------------
extern "C" void kernel_launch(void* const* d_in, const int* in_sizes, int n_in,
                              void* d_out, int out_size) {
    const float* V   = (const float*)d_in[0];
    const float* U1v = (const float*)d_in[1];
    const float* U1g = (const float*)d_in[2];
    const float* U1b = (const float*)d_in[3];
    const float* U2v = (const float*)d_in[4];
    const float* U2g = (const float*)d_in[5];
    const float* U2b = (const float*)d_in[6];
    const float* Wl  = (const float*)d_in[7];
    const float* bl  = (const float*)d_in[8];
    const float* gm  = (const float*)d_in[9];
    const float* bt  = (const float*)d_in[10];
    float* out = (float*)d_out;

    cudaFuncSetAttribute(k_proj, cudaFuncAttributeMaxDynamicSharedMemorySize, SM1_FLOATS * 4);

    k_prep<<<10, 256>>>(U1v, U1g, U1b, U2v, U2g, U2b);
    k_proj<<<dim3(32, 32), 256, SM1_FLOATS * 4>>>(V);
    k_corrsum<<<dim3(16, 32), 256>>>(V);
    k_final<<<16, 256>>>(Wl, bl, gm, bt, out);
}